// round 15
// baseline (speedup 1.0000x reference)
#include <cuda_runtime.h>
#include <cstdint>

#define B 32
#define L 512
#define T 4096
#define D 384
#define D4 (D / 4)          // 96 float4 per row
#define RPT 8               // rows per thread in expand kernel
#define RPB (RPT * 4)       // 32 rows per block (block y-dim = 4)
#define WARPS 12            // 384 threads
#define SLICE_BYTES (RPB * D * 4 / WARPS)   // 4096 B per warp slice

// Scratch (no allocations allowed in kernel_launch)
__device__ int g_idx[B * T];

// Kernel 1: per-batch inclusive scan of durations (warp-shuffle scan) +
// scatter token index into the output-slot map, then prefill the invalid
// tail [total, T) with -1 so expand needs no bounds logic at all.
__global__ void scan_scatter_kernel(const int* __restrict__ dur,
                                    const int* __restrict__ mask,
                                    float* __restrict__ out_tail,
                                    int write_tail) {
    __shared__ int wsum[16];
    const int b    = blockIdx.x;
    const int t    = threadIdx.x;        // 0..511
    const int lane = t & 31;
    const int w    = t >> 5;             // 0..15

    const int d = dur[b * L + t];        // EXPAND_SCALE=1.0 -> round(d)=d
    int x = d;

    #pragma unroll
    for (int off = 1; off < 32; off <<= 1) {
        int n = __shfl_up_sync(0xFFFFFFFFu, x, off);
        if (lane >= off) x += n;
    }
    if (lane == 31) wsum[w] = x;
    __syncthreads();

    if (w == 0 && lane < 16) {
        int y = wsum[lane];
        #pragma unroll
        for (int off = 1; off < 16; off <<= 1) {
            int n = __shfl_up_sync(0xFFFFu, y, off);
            if (lane >= off) y += n;
        }
        wsum[lane] = y;
    }
    __syncthreads();

    const int end   = x + (w > 0 ? wsum[w - 1] : 0);
    const int start = end - d;
    const int val   = mask[b * L + t] ? -1 : t;
    for (int j = start; j < end; ++j)
        g_idx[b * T + j] = val;

    const int total = wsum[15];
    for (int j = total + t; j < T; j += L)
        g_idx[b * T + j] = -1;

    if (write_tail)
        out_tail[b * L + t] = (float)d;   // exp_dur as second output

    cudaTriggerProgrammaticLaunchCompletion();
}

// Kernel 2: async gather-expand.
//  - 8 cp.async (16B) per thread stage gathered seq rows into a 48KB smem tile
//    (pad rows get STS zeros). No destination registers -> deep MLP.
//  - Each warp bulk-stores its contiguous 4KB slice, then fully drains the
//    bulk group before exit (no in-flight async state at kernel end).
__global__ __launch_bounds__(D4 * 4)
void expand_kernel(const float4* __restrict__ seq,
                   float4* __restrict__ out) {
    __shared__ __align__(128) float4 tile[RPB * D4];   // 48KB

    const int base = blockIdx.x * RPB;
    const int c    = threadIdx.x;           // 0..95
    const int y    = threadIdx.y;           // 0..3
    const int b    = base >> 12;            // batch for all 32 rows
    const int tid  = y * D4 + c;
    const int wid  = tid >> 5;
    const int lane = tid & 31;

    // Wait for scan_scatter results (PDL overlap hides launch latency)
    cudaGridDependencySynchronize();

    int idx[RPT];
    #pragma unroll
    for (int i = 0; i < RPT; ++i)
        idx[i] = g_idx[base + y + 4 * i];   // complete predicate: <0 == pad

    const uint32_t smem_base = (uint32_t)__cvta_generic_to_shared(tile);

    #pragma unroll
    for (int i = 0; i < RPT; ++i) {
        const int rl = y + 4 * i;                       // smem row 0..31
        const uint32_t daddr = smem_base + (rl * D4 + c) * 16;
        if (idx[i] >= 0) {
            const float4* src = seq + ((size_t)(b * L + idx[i]) * D4 + c);
            asm volatile("cp.async.cg.shared.global [%0], [%1], 16;"
                         :: "r"(daddr), "l"(src) : "memory");
        } else {
            asm volatile("st.shared.v4.b32 [%0], {%1,%1,%1,%1};"
                         :: "r"(daddr), "r"(0) : "memory");
        }
    }
    asm volatile("cp.async.commit_group;" ::: "memory");
    asm volatile("cp.async.wait_group 0;" ::: "memory");
    __syncthreads();

    // Per-warp bulk store of a contiguous 4KB slice of the 48KB tile.
    if (lane == 0) {
        char* dst = (char*)(out + (size_t)base * D4) + wid * SLICE_BYTES;
        const uint32_t src_s = smem_base + wid * SLICE_BYTES;
        asm volatile("cp.async.bulk.global.shared::cta.bulk_group [%0], [%1], %2;"
                     :: "l"(dst), "r"(src_s), "n"(SLICE_BYTES) : "memory");
        asm volatile("cp.async.bulk.commit_group;" ::: "memory");
        // Fully drain: no async state in flight at kernel exit.
        asm volatile("cp.async.bulk.wait_group 0;" ::: "memory");
    }
    __syncthreads();
}

extern "C" void kernel_launch(void* const* d_in, const int* in_sizes, int n_in,
                              void* d_out, int out_size) {
    const float* seq  = (const float*)d_in[0];
    const int*   dur  = (const int*)d_in[1];    // int64 in ref -> int32 here
    const int*   mask = (const int*)d_in[2];    // bool in ref -> int32 here
    float* out = (float*)d_out;

    const long long main_elems = (long long)B * T * D;
    const int write_tail = (out_size >= main_elems + (long long)B * L) ? 1 : 0;

    scan_scatter_kernel<<<B, L>>>(dur, mask, out + main_elems, write_tail);

    cudaLaunchConfig_t cfg = {};
    cfg.gridDim  = dim3((B * T) / RPB, 1, 1);
    cfg.blockDim = dim3(D4, 4, 1);
    cfg.dynamicSmemBytes = 0;
    cfg.stream = 0;
    cudaLaunchAttribute attr;
    attr.id = cudaLaunchAttributeProgrammaticStreamSerialization;
    attr.val.programmaticStreamSerializationAllowed = 1;
    cfg.attrs = &attr;
    cfg.numAttrs = 1;
    cudaLaunchKernelEx(&cfg, expand_kernel, (const float4*)seq, (float4*)out);
}